// round 1
// baseline (speedup 1.0000x reference)
#include <cuda_runtime.h>
#include <cuda_bf16.h>

#define KS 5
#define PADR 2
#define TX 32
#define TY 8
#define W 512
#define H 512
#define SMW (TX + 2*PADR)   // 36
#define SMH (TY + 2*PADR)   // 12

// exp(-0.5 * t) via ex2.approx:  2^(t * -0.5*log2(e))
__device__ __forceinline__ float exp_neg_half(float t) {
    float r;
    asm("ex2.approx.ftz.f32 %0, %1;" : "=f"(r) : "f"(t * -0.72134752044448170f));
    return r;
}

__device__ __forceinline__ int reflect_idx(int i, int n) {
    // pad <= 2, single reflection suffices for n=512
    if (i < 0) i = -i;
    if (i >= n) i = 2 * n - 2 - i;
    return i;
}

__global__ __launch_bounds__(TX * TY)
void bilateral_kernel(const float* __restrict__ x,
                      const float* __restrict__ ws,
                      float* __restrict__ out) {
    __shared__ float tile[SMH][SMW];
    __shared__ float wsp[KS * KS];

    const int tx = threadIdx.x;
    const int ty = threadIdx.y;
    const int tid = ty * TX + tx;

    const int x0 = blockIdx.x * TX;
    const int y0 = blockIdx.y * TY;
    const long plane = (long)blockIdx.z * (H * W);

    if (tid < KS * KS) wsp[tid] = ws[tid];

    // cooperative tile load with reflect padding
    #pragma unroll
    for (int i = tid; i < SMH * SMW; i += TX * TY) {
        int r = i / SMW;
        int c = i % SMW;
        int gy = reflect_idx(y0 + r - PADR, H);
        int gx = reflect_idx(x0 + c - PADR, W);
        tile[r][c] = x[plane + (long)gy * W + gx];
    }
    __syncthreads();

    const float c0 = tile[ty + PADR][tx + PADR];

    float num = 0.0f;
    float den = 0.0f;
    #pragma unroll
    for (int ki = 0; ki < KS; ki++) {
        #pragma unroll
        for (int kj = 0; kj < KS; kj++) {
            float p = tile[ty + ki][tx + kj];
            float d = p - c0;
            float e = exp_neg_half(d * d) * wsp[ki * KS + kj];
            num = fmaf(e, p, num);
            den += e;
        }
    }

    out[plane + (long)(y0 + ty) * W + (x0 + tx)] = __fdividef(num, den);
}

extern "C" void kernel_launch(void* const* d_in, const int* in_sizes, int n_in,
                              void* d_out, int out_size) {
    const float* x  = (const float*)d_in[0];
    const float* ws = (const float*)d_in[1];
    float* out = (float*)d_out;

    int nplanes = in_sizes[0] / (H * W);   // B*C = 12
    dim3 block(TX, TY);
    dim3 grid(W / TX, H / TY, nplanes);
    bilateral_kernel<<<grid, block>>>(x, ws, out);
}

// round 2
// speedup vs baseline: 1.3226x; 1.3226x over previous
#include <cuda_runtime.h>
#include <cuda_bf16.h>

#define KS 5
#define PADR 2
#define TX 32
#define TYB 4          // threads in y
#define RY 4           // output rows per thread
#define W 512
#define H 512
#define TILE_H (TYB*RY + 2*PADR)   // 20
#define TILE_W (TX + 2*PADR)       // 36

// A = sqrt(0.5 * log2(e))  so that  s^2 = 0.5*log2(e)*d^2
#define AA 0.84932184032f

__device__ __forceinline__ float ex2f(float t) {
    float r;
    asm("ex2.approx.ftz.f32 %0, %1;" : "=f"(r) : "f"(t));
    return r;
}
__device__ __forceinline__ float lg2f(float t) {
    float r;
    asm("lg2.approx.f32 %0, %1;" : "=f"(r) : "f"(t));
    return r;
}

__device__ __forceinline__ int reflect_idx(int i, int n) {
    if (i < 0) i = -i;
    if (i >= n) i = 2 * n - 2 - i;
    return i;
}

__global__ __launch_bounds__(TX * TYB)
void bilateral_kernel(const float* __restrict__ x,
                      const float* __restrict__ ws,
                      float* __restrict__ out) {
    __shared__ float tile[TILE_H][TILE_W];
    __shared__ float lws[KS * KS];   // log2(weight_space)
    __shared__ float wsc;            // raw center weight

    const int tx  = threadIdx.x;
    const int ty  = threadIdx.y;
    const int tid = ty * TX + tx;

    const int x0 = blockIdx.x * TX;
    const int y0 = blockIdx.y * (TYB * RY);
    const long plane = (long)blockIdx.z * (H * W);

    if (tid < KS * KS) {
        float w = ws[tid];
        lws[tid] = lg2f(w);
        if (tid == 12) wsc = w;
    }

    // cooperative tile load with reflect padding (720 elems / 128 thr = 6 rounds)
    #pragma unroll
    for (int i = tid; i < TILE_H * TILE_W; i += TX * TYB) {
        int r = i / TILE_W;
        int c = i - r * TILE_W;
        int gy = reflect_idx(y0 + r - PADR, H);
        int gx = reflect_idx(x0 + c - PADR, W);
        tile[r][c] = x[plane + (long)gy * W + gx];
    }
    __syncthreads();

    const int b = ty * RY;           // first window row (tile coords) for this thread

    // 5x5 register ring window; prologue: rows 0..3
    float w0[5], w1[5], w2[5], w3[5], w4[5];
    #pragma unroll
    for (int j = 0; j < 5; j++) {
        w0[j] = tile[b + 0][tx + j];
        w1[j] = tile[b + 1][tx + j];
        w2[j] = tile[b + 2][tx + j];
        w3[j] = tile[b + 3][tx + j];
    }

    float* ring[5] = {w0, w1, w2, w3, w4};
    const float wcen = wsc;

    long obase = plane + (long)(y0 + b) * W + (x0 + tx);

    #pragma unroll
    for (int rr = 0; rr < RY; rr++) {
        // load the new bottom row into ring slot (rr+4)%5
        float* wn = ring[(rr + 4) % 5];
        #pragma unroll
        for (int j = 0; j < 5; j++) wn[j] = tile[b + rr + 4][tx + j];

        const float c0    = ring[(rr + 2) % 5][2];
        const float negcs = -c0 * AA;

        float num = 0.0f, den = 0.0f;
        #pragma unroll
        for (int ki = 0; ki < 5; ki++) {
            float* wr = ring[(rr + ki) % 5];
            #pragma unroll
            for (int kj = 0; kj < 5; kj++) {
                if (ki == 2 && kj == 2) {
                    num = fmaf(wcen, c0, num);
                    den += wcen;
                } else {
                    float p = wr[kj];
                    float s = fmaf(p, AA, negcs);
                    float t = fmaf(-s, s, lws[ki * KS + kj]);
                    float e = ex2f(t);
                    num = fmaf(e, p, num);
                    den += e;
                }
            }
        }
        out[obase + (long)rr * W] = __fdividef(num, den);
    }
}

extern "C" void kernel_launch(void* const* d_in, const int* in_sizes, int n_in,
                              void* d_out, int out_size) {
    const float* x  = (const float*)d_in[0];
    const float* ws = (const float*)d_in[1];
    float* out = (float*)d_out;

    int nplanes = in_sizes[0] / (H * W);   // B*C = 12
    dim3 block(TX, TYB);
    dim3 grid(W / TX, H / (TYB * RY), nplanes);
    bilateral_kernel<<<grid, block>>>(x, ws, out);
}